// round 15
// baseline (speedup 1.0000x reference)
#include <cuda_runtime.h>
#include <cuda_bf16.h>

#define NB 2
#define LSEQ 4096
#define DMODEL 512
#define NHEAD 8
#define DHEAD 64

static __device__ float g_Q[NB * LSEQ * DMODEL];
static __device__ float g_K[NB * LSEQ * DMODEL];
static __device__ float g_V[NB * LSEQ * DMODEL];
static __device__ float g_O[NB * LSEQ * DMODEL];

// ---------------------------------------------------------------------------
// C[M,N] = A[M,K] @ B[N,K]^T + bias   (all row-major, NT GEMM)
// 64x64 C tile per block, 256 threads, 4x4 micro-tile per thread.
// B is stored transposed in SMEM so compute-phase reads are conflict-free.
// ---------------------------------------------------------------------------
__global__ __launch_bounds__(256)
void gemm_nt_bias(const float* __restrict__ A, const float* __restrict__ B,
                  const float* __restrict__ bias, float* __restrict__ C,
                  int M, int N, int Kd)
{
    __shared__ float As[64 * 64];
    __shared__ float Bst[64 * 64];   // [k][n]

    const int tid = threadIdx.x;
    const int ty = tid >> 4;         // 0..15  (row group)
    const int tx = tid & 15;         // 0..15  (col group)
    const int n0 = blockIdx.x * 64;
    const int m0 = blockIdx.y * 64;

    float acc[4][4];
#pragma unroll
    for (int i = 0; i < 4; ++i)
#pragma unroll
        for (int j = 0; j < 4; ++j) acc[i][j] = 0.f;

    for (int kc = 0; kc < Kd; kc += 64) {
        __syncthreads();
#pragma unroll
        for (int e = tid; e < 1024; e += 256) {
            int r  = e >> 4;
            int d4 = (e & 15) << 2;
            float4 av = *(const float4*)(A + (size_t)(m0 + r) * Kd + kc + d4);
            *(float4*)&As[r * 64 + d4] = av;
            float4 bv = *(const float4*)(B + (size_t)(n0 + r) * Kd + kc + d4);
            Bst[(d4 + 0) * 64 + r] = bv.x;
            Bst[(d4 + 1) * 64 + r] = bv.y;
            Bst[(d4 + 2) * 64 + r] = bv.z;
            Bst[(d4 + 3) * 64 + r] = bv.w;
        }
        __syncthreads();

#pragma unroll
        for (int k = 0; k < 64; k += 4) {
            float4 b0 = *(const float4*)&Bst[(k + 0) * 64 + tx * 4];
            float4 b1 = *(const float4*)&Bst[(k + 1) * 64 + tx * 4];
            float4 b2 = *(const float4*)&Bst[(k + 2) * 64 + tx * 4];
            float4 b3 = *(const float4*)&Bst[(k + 3) * 64 + tx * 4];
#pragma unroll
            for (int i = 0; i < 4; ++i) {
                float4 a = *(const float4*)&As[(ty * 4 + i) * 64 + k];
                acc[i][0] += a.x * b0.x + a.y * b1.x + a.z * b2.x + a.w * b3.x;
                acc[i][1] += a.x * b0.y + a.y * b1.y + a.z * b2.y + a.w * b3.y;
                acc[i][2] += a.x * b0.z + a.y * b1.z + a.z * b2.z + a.w * b3.z;
                acc[i][3] += a.x * b0.w + a.y * b1.w + a.z * b2.w + a.w * b3.w;
            }
        }
    }

    float4 bi = *(const float4*)(bias + n0 + tx * 4);
#pragma unroll
    for (int i = 0; i < 4; ++i) {
        float4 o = make_float4(acc[i][0] + bi.x, acc[i][1] + bi.y,
                               acc[i][2] + bi.z, acc[i][3] + bi.w);
        *(float4*)(C + (size_t)(m0 + ty * 4 + i) * N + n0 + tx * 4) = o;
    }
}

// ---------------------------------------------------------------------------
// Flash attention, fp32. One block per (q-tile of 64 rows, batch*head).
// 256 threads; thread (ty,tx) owns rows ty*4+i and cols/dims tx*4+j.
// Online softmax; P tile is written back into the K smem buffer (48KB total).
// ---------------------------------------------------------------------------
__global__ __launch_bounds__(256)
void flash_attn(const float* __restrict__ Q, const float* __restrict__ K,
                const float* __restrict__ V, const int* __restrict__ mask,
                float* __restrict__ O)
{
    __shared__ float Qs[64 * 64];    // [q][d]
    __shared__ float KPs[64 * 64];   // [d][k] for K^T, then reused as P [q][k]
    __shared__ float Vs[64 * 64];    // [k][d]

    const int tid = threadIdx.x;
    const int ty = tid >> 4;
    const int tx = tid & 15;
    const int b  = blockIdx.y >> 3;
    const int h  = blockIdx.y & 7;
    const int q0 = blockIdx.x * 64;

    const float* Qb = Q + (size_t)(b * LSEQ + q0) * DMODEL + h * DHEAD;
    const float* Kb = K + (size_t)b * LSEQ * DMODEL + h * DHEAD;
    const float* Vb = V + (size_t)b * LSEQ * DMODEL + h * DHEAD;
    const int*   mb = mask + b * LSEQ;

#pragma unroll
    for (int e = tid; e < 1024; e += 256) {
        int r  = e >> 4;
        int d4 = (e & 15) << 2;
        *(float4*)&Qs[r * 64 + d4] = *(const float4*)(Qb + (size_t)r * DMODEL + d4);
    }

    float acc[4][4];
#pragma unroll
    for (int i = 0; i < 4; ++i)
#pragma unroll
        for (int j = 0; j < 4; ++j) acc[i][j] = 0.f;

    float mrow[4], lrow[4];
#pragma unroll
    for (int i = 0; i < 4; ++i) { mrow[i] = -1e30f; lrow[i] = 0.f; }

    for (int kt = 0; kt < LSEQ; kt += 64) {
        __syncthreads();   // previous iteration done with KPs/Vs
#pragma unroll
        for (int e = tid; e < 1024; e += 256) {
            int r  = e >> 4;
            int d4 = (e & 15) << 2;
            float4 kv = *(const float4*)(Kb + (size_t)(kt + r) * DMODEL + d4);
            KPs[(d4 + 0) * 64 + r] = kv.x;
            KPs[(d4 + 1) * 64 + r] = kv.y;
            KPs[(d4 + 2) * 64 + r] = kv.z;
            KPs[(d4 + 3) * 64 + r] = kv.w;
            *(float4*)&Vs[r * 64 + d4] =
                *(const float4*)(Vb + (size_t)(kt + r) * DMODEL + d4);
        }
        __syncthreads();

        // ---- S = Q K^T (64x64 tile, 4x4 per thread) ----
        float s[4][4];
#pragma unroll
        for (int i = 0; i < 4; ++i)
#pragma unroll
            for (int j = 0; j < 4; ++j) s[i][j] = 0.f;

#pragma unroll
        for (int d = 0; d < 64; d += 4) {
            float4 b0 = *(const float4*)&KPs[(d + 0) * 64 + tx * 4];
            float4 b1 = *(const float4*)&KPs[(d + 1) * 64 + tx * 4];
            float4 b2 = *(const float4*)&KPs[(d + 2) * 64 + tx * 4];
            float4 b3 = *(const float4*)&KPs[(d + 3) * 64 + tx * 4];
#pragma unroll
            for (int i = 0; i < 4; ++i) {
                float4 a = *(const float4*)&Qs[(ty * 4 + i) * 64 + d];
                s[i][0] += a.x * b0.x + a.y * b1.x + a.z * b2.x + a.w * b3.x;
                s[i][1] += a.x * b0.y + a.y * b1.y + a.z * b2.y + a.w * b3.y;
                s[i][2] += a.x * b0.z + a.y * b1.z + a.z * b2.z + a.w * b3.z;
                s[i][3] += a.x * b0.w + a.y * b1.w + a.z * b2.w + a.w * b3.w;
            }
        }

        // ---- scale + mask (same order as reference) ----
        const int4 mv = *(const int4*)(mb + kt + tx * 4);
#pragma unroll
        for (int i = 0; i < 4; ++i) {
            s[i][0] = (mv.x == 0) ? -1000000000.0f : s[i][0] * 0.125f;
            s[i][1] = (mv.y == 0) ? -1000000000.0f : s[i][1] * 0.125f;
            s[i][2] = (mv.z == 0) ? -1000000000.0f : s[i][2] * 0.125f;
            s[i][3] = (mv.w == 0) ? -1000000000.0f : s[i][3] * 0.125f;
        }

        // ---- online softmax update (row = 16 lanes, shfl reduce) ----
#pragma unroll
        for (int i = 0; i < 4; ++i) {
            float mx = fmaxf(fmaxf(s[i][0], s[i][1]), fmaxf(s[i][2], s[i][3]));
            mx = fmaxf(mx, __shfl_xor_sync(0xffffffffu, mx, 1));
            mx = fmaxf(mx, __shfl_xor_sync(0xffffffffu, mx, 2));
            mx = fmaxf(mx, __shfl_xor_sync(0xffffffffu, mx, 4));
            mx = fmaxf(mx, __shfl_xor_sync(0xffffffffu, mx, 8));
            float mnew = fmaxf(mrow[i], mx);
            float corr = __expf(mrow[i] - mnew);
            mrow[i] = mnew;
            float rs = 0.f;
#pragma unroll
            for (int j = 0; j < 4; ++j) {
                s[i][j] = __expf(s[i][j] - mnew);
                rs += s[i][j];
            }
            rs += __shfl_xor_sync(0xffffffffu, rs, 1);
            rs += __shfl_xor_sync(0xffffffffu, rs, 2);
            rs += __shfl_xor_sync(0xffffffffu, rs, 4);
            rs += __shfl_xor_sync(0xffffffffu, rs, 8);
            lrow[i] = lrow[i] * corr + rs;
#pragma unroll
            for (int j = 0; j < 4; ++j) acc[i][j] *= corr;
        }

        // ---- write P into KPs (K^T no longer needed) ----
        __syncthreads();
#pragma unroll
        for (int i = 0; i < 4; ++i)
            *(float4*)&KPs[(ty * 4 + i) * 64 + tx * 4] =
                make_float4(s[i][0], s[i][1], s[i][2], s[i][3]);
        __syncthreads();

        // ---- acc += P @ V ----
#pragma unroll
        for (int k = 0; k < 64; k += 4) {
            float4 v0 = *(const float4*)&Vs[(k + 0) * 64 + tx * 4];
            float4 v1 = *(const float4*)&Vs[(k + 1) * 64 + tx * 4];
            float4 v2 = *(const float4*)&Vs[(k + 2) * 64 + tx * 4];
            float4 v3 = *(const float4*)&Vs[(k + 3) * 64 + tx * 4];
#pragma unroll
            for (int i = 0; i < 4; ++i) {
                float4 p = *(const float4*)&KPs[(ty * 4 + i) * 64 + k];
                acc[i][0] += p.x * v0.x + p.y * v1.x + p.z * v2.x + p.w * v3.x;
                acc[i][1] += p.x * v0.y + p.y * v1.y + p.z * v2.y + p.w * v3.y;
                acc[i][2] += p.x * v0.z + p.y * v1.z + p.z * v2.z + p.w * v3.z;
                acc[i][3] += p.x * v0.w + p.y * v1.w + p.z * v2.w + p.w * v3.w;
            }
        }
    }

    float* Ob = O + (size_t)(b * LSEQ + q0) * DMODEL + h * DHEAD;
#pragma unroll
    for (int i = 0; i < 4; ++i) {
        float inv = 1.f / lrow[i];
        float4 o = make_float4(acc[i][0] * inv, acc[i][1] * inv,
                               acc[i][2] * inv, acc[i][3] * inv);
        *(float4*)(Ob + (size_t)(ty * 4 + i) * DMODEL + tx * 4) = o;
    }
}

// ---------------------------------------------------------------------------
extern "C" void kernel_launch(void* const* d_in, const int* in_sizes, int n_in,
                              void* d_out, int out_size)
{
    const float* query = (const float*)d_in[0];
    const float* key   = (const float*)d_in[1];
    const float* value = (const float*)d_in[2];
    const int*   mask  = (const int*)d_in[3];
    const float* Wq = (const float*)d_in[4];
    const float* bq = (const float*)d_in[5];
    const float* Wk = (const float*)d_in[6];
    const float* bk = (const float*)d_in[7];
    const float* Wv = (const float*)d_in[8];
    const float* bv = (const float*)d_in[9];
    const float* Wo = (const float*)d_in[10];
    const float* bo = (const float*)d_in[11];
    float* out = (float*)d_out;

    float *pQ, *pK, *pV, *pO;
    cudaGetSymbolAddress((void**)&pQ, g_Q);
    cudaGetSymbolAddress((void**)&pK, g_K);
    cudaGetSymbolAddress((void**)&pV, g_V);
    cudaGetSymbolAddress((void**)&pO, g_O);

    const int M = NB * LSEQ;           // 8192
    dim3 gg(DMODEL / 64, M / 64);      // (8, 128)
    dim3 bb(256);

    gemm_nt_bias<<<gg, bb>>>(query, Wq, bq, pQ, M, DMODEL, DMODEL);
    gemm_nt_bias<<<gg, bb>>>(key,   Wk, bk, pK, M, DMODEL, DMODEL);
    gemm_nt_bias<<<gg, bb>>>(value, Wv, bv, pV, M, DMODEL, DMODEL);

    flash_attn<<<dim3(LSEQ / 64, NB * NHEAD), bb>>>(pQ, pK, pV, mask, pO);

    gemm_nt_bias<<<gg, bb>>>(pO, Wo, bo, out, M, DMODEL, DMODEL);
}

// round 16
// speedup vs baseline: 1.0001x; 1.0001x over previous
#include <cuda_runtime.h>
#include <cuda_bf16.h>

#define NB 2
#define LSEQ 4096
#define DMODEL 512
#define NHEAD 8
#define DHEAD 64

static __device__ float g_Q[NB * LSEQ * DMODEL];
static __device__ float g_K[NB * LSEQ * DMODEL];
static __device__ float g_V[NB * LSEQ * DMODEL];
static __device__ float g_O[NB * LSEQ * DMODEL];

// ---------------------------------------------------------------------------
// C[M,N] = A[M,K] @ B[N,K]^T + bias   (all row-major, NT GEMM)
// 64x64 C tile per block, 256 threads, 4x4 micro-tile per thread.
// B is stored transposed in SMEM so compute-phase reads are conflict-free.
// ---------------------------------------------------------------------------
__global__ __launch_bounds__(256)
void gemm_nt_bias(const float* __restrict__ A, const float* __restrict__ B,
                  const float* __restrict__ bias, float* __restrict__ C,
                  int M, int N, int Kd)
{
    __shared__ float As[64 * 64];
    __shared__ float Bst[64 * 64];   // [k][n]

    const int tid = threadIdx.x;
    const int ty = tid >> 4;         // 0..15  (row group)
    const int tx = tid & 15;         // 0..15  (col group)
    const int n0 = blockIdx.x * 64;
    const int m0 = blockIdx.y * 64;

    float acc[4][4];
#pragma unroll
    for (int i = 0; i < 4; ++i)
#pragma unroll
        for (int j = 0; j < 4; ++j) acc[i][j] = 0.f;

    for (int kc = 0; kc < Kd; kc += 64) {
        __syncthreads();
#pragma unroll
        for (int e = tid; e < 1024; e += 256) {
            int r  = e >> 4;
            int d4 = (e & 15) << 2;
            float4 av = *(const float4*)(A + (size_t)(m0 + r) * Kd + kc + d4);
            *(float4*)&As[r * 64 + d4] = av;
            float4 bv = *(const float4*)(B + (size_t)(n0 + r) * Kd + kc + d4);
            Bst[(d4 + 0) * 64 + r] = bv.x;
            Bst[(d4 + 1) * 64 + r] = bv.y;
            Bst[(d4 + 2) * 64 + r] = bv.z;
            Bst[(d4 + 3) * 64 + r] = bv.w;
        }
        __syncthreads();

#pragma unroll
        for (int k = 0; k < 64; k += 4) {
            float4 b0 = *(const float4*)&Bst[(k + 0) * 64 + tx * 4];
            float4 b1 = *(const float4*)&Bst[(k + 1) * 64 + tx * 4];
            float4 b2 = *(const float4*)&Bst[(k + 2) * 64 + tx * 4];
            float4 b3 = *(const float4*)&Bst[(k + 3) * 64 + tx * 4];
#pragma unroll
            for (int i = 0; i < 4; ++i) {
                float4 a = *(const float4*)&As[(ty * 4 + i) * 64 + k];
                acc[i][0] += a.x * b0.x + a.y * b1.x + a.z * b2.x + a.w * b3.x;
                acc[i][1] += a.x * b0.y + a.y * b1.y + a.z * b2.y + a.w * b3.y;
                acc[i][2] += a.x * b0.z + a.y * b1.z + a.z * b2.z + a.w * b3.z;
                acc[i][3] += a.x * b0.w + a.y * b1.w + a.z * b2.w + a.w * b3.w;
            }
        }
    }

    float4 bi = *(const float4*)(bias + n0 + tx * 4);
#pragma unroll
    for (int i = 0; i < 4; ++i) {
        float4 o = make_float4(acc[i][0] + bi.x, acc[i][1] + bi.y,
                               acc[i][2] + bi.z, acc[i][3] + bi.w);
        *(float4*)(C + (size_t)(m0 + ty * 4 + i) * N + n0 + tx * 4) = o;
    }
}

// ---------------------------------------------------------------------------
// Flash attention, fp32. One block per (q-tile of 64 rows, batch*head).
// 256 threads; thread (ty,tx) owns rows ty*4+i and cols/dims tx*4+j.
// Online softmax; P tile is written back into the K smem buffer (48KB total).
// ---------------------------------------------------------------------------
__global__ __launch_bounds__(256)
void flash_attn(const float* __restrict__ Q, const float* __restrict__ K,
                const float* __restrict__ V, const int* __restrict__ mask,
                float* __restrict__ O)
{
    __shared__ float Qs[64 * 64];    // [q][d]
    __shared__ float KPs[64 * 64];   // [d][k] for K^T, then reused as P [q][k]
    __shared__ float Vs[64 * 64];    // [k][d]

    const int tid = threadIdx.x;
    const int ty = tid >> 4;
    const int tx = tid & 15;
    const int b  = blockIdx.y >> 3;
    const int h  = blockIdx.y & 7;
    const int q0 = blockIdx.x * 64;

    const float* Qb = Q + (size_t)(b * LSEQ + q0) * DMODEL + h * DHEAD;
    const float* Kb = K + (size_t)b * LSEQ * DMODEL + h * DHEAD;
    const float* Vb = V + (size_t)b * LSEQ * DMODEL + h * DHEAD;
    const int*   mb = mask + b * LSEQ;

#pragma unroll
    for (int e = tid; e < 1024; e += 256) {
        int r  = e >> 4;
        int d4 = (e & 15) << 2;
        *(float4*)&Qs[r * 64 + d4] = *(const float4*)(Qb + (size_t)r * DMODEL + d4);
    }

    float acc[4][4];
#pragma unroll
    for (int i = 0; i < 4; ++i)
#pragma unroll
        for (int j = 0; j < 4; ++j) acc[i][j] = 0.f;

    float mrow[4], lrow[4];
#pragma unroll
    for (int i = 0; i < 4; ++i) { mrow[i] = -1e30f; lrow[i] = 0.f; }

    for (int kt = 0; kt < LSEQ; kt += 64) {
        __syncthreads();   // previous iteration done with KPs/Vs
#pragma unroll
        for (int e = tid; e < 1024; e += 256) {
            int r  = e >> 4;
            int d4 = (e & 15) << 2;
            float4 kv = *(const float4*)(Kb + (size_t)(kt + r) * DMODEL + d4);
            KPs[(d4 + 0) * 64 + r] = kv.x;
            KPs[(d4 + 1) * 64 + r] = kv.y;
            KPs[(d4 + 2) * 64 + r] = kv.z;
            KPs[(d4 + 3) * 64 + r] = kv.w;
            *(float4*)&Vs[r * 64 + d4] =
                *(const float4*)(Vb + (size_t)(kt + r) * DMODEL + d4);
        }
        __syncthreads();

        // ---- S = Q K^T (64x64 tile, 4x4 per thread) ----
        float s[4][4];
#pragma unroll
        for (int i = 0; i < 4; ++i)
#pragma unroll
            for (int j = 0; j < 4; ++j) s[i][j] = 0.f;

#pragma unroll
        for (int d = 0; d < 64; d += 4) {
            float4 b0 = *(const float4*)&KPs[(d + 0) * 64 + tx * 4];
            float4 b1 = *(const float4*)&KPs[(d + 1) * 64 + tx * 4];
            float4 b2 = *(const float4*)&KPs[(d + 2) * 64 + tx * 4];
            float4 b3 = *(const float4*)&KPs[(d + 3) * 64 + tx * 4];
#pragma unroll
            for (int i = 0; i < 4; ++i) {
                float4 a = *(const float4*)&Qs[(ty * 4 + i) * 64 + d];
                s[i][0] += a.x * b0.x + a.y * b1.x + a.z * b2.x + a.w * b3.x;
                s[i][1] += a.x * b0.y + a.y * b1.y + a.z * b2.y + a.w * b3.y;
                s[i][2] += a.x * b0.z + a.y * b1.z + a.z * b2.z + a.w * b3.z;
                s[i][3] += a.x * b0.w + a.y * b1.w + a.z * b2.w + a.w * b3.w;
            }
        }

        // ---- scale + mask (same order as reference) ----
        const int4 mv = *(const int4*)(mb + kt + tx * 4);
#pragma unroll
        for (int i = 0; i < 4; ++i) {
            s[i][0] = (mv.x == 0) ? -1000000000.0f : s[i][0] * 0.125f;
            s[i][1] = (mv.y == 0) ? -1000000000.0f : s[i][1] * 0.125f;
            s[i][2] = (mv.z == 0) ? -1000000000.0f : s[i][2] * 0.125f;
            s[i][3] = (mv.w == 0) ? -1000000000.0f : s[i][3] * 0.125f;
        }

        // ---- online softmax update (row = 16 lanes, shfl reduce) ----
#pragma unroll
        for (int i = 0; i < 4; ++i) {
            float mx = fmaxf(fmaxf(s[i][0], s[i][1]), fmaxf(s[i][2], s[i][3]));
            mx = fmaxf(mx, __shfl_xor_sync(0xffffffffu, mx, 1));
            mx = fmaxf(mx, __shfl_xor_sync(0xffffffffu, mx, 2));
            mx = fmaxf(mx, __shfl_xor_sync(0xffffffffu, mx, 4));
            mx = fmaxf(mx, __shfl_xor_sync(0xffffffffu, mx, 8));
            float mnew = fmaxf(mrow[i], mx);
            float corr = __expf(mrow[i] - mnew);
            mrow[i] = mnew;
            float rs = 0.f;
#pragma unroll
            for (int j = 0; j < 4; ++j) {
                s[i][j] = __expf(s[i][j] - mnew);
                rs += s[i][j];
            }
            rs += __shfl_xor_sync(0xffffffffu, rs, 1);
            rs += __shfl_xor_sync(0xffffffffu, rs, 2);
            rs += __shfl_xor_sync(0xffffffffu, rs, 4);
            rs += __shfl_xor_sync(0xffffffffu, rs, 8);
            lrow[i] = lrow[i] * corr + rs;
#pragma unroll
            for (int j = 0; j < 4; ++j) acc[i][j] *= corr;
        }

        // ---- write P into KPs (K^T no longer needed) ----
        __syncthreads();
#pragma unroll
        for (int i = 0; i < 4; ++i)
            *(float4*)&KPs[(ty * 4 + i) * 64 + tx * 4] =
                make_float4(s[i][0], s[i][1], s[i][2], s[i][3]);
        __syncthreads();

        // ---- acc += P @ V ----
#pragma unroll
        for (int k = 0; k < 64; k += 4) {
            float4 v0 = *(const float4*)&Vs[(k + 0) * 64 + tx * 4];
            float4 v1 = *(const float4*)&Vs[(k + 1) * 64 + tx * 4];
            float4 v2 = *(const float4*)&Vs[(k + 2) * 64 + tx * 4];
            float4 v3 = *(const float4*)&Vs[(k + 3) * 64 + tx * 4];
#pragma unroll
            for (int i = 0; i < 4; ++i) {
                float4 p = *(const float4*)&KPs[(ty * 4 + i) * 64 + k];
                acc[i][0] += p.x * v0.x + p.y * v1.x + p.z * v2.x + p.w * v3.x;
                acc[i][1] += p.x * v0.y + p.y * v1.y + p.z * v2.y + p.w * v3.y;
                acc[i][2] += p.x * v0.z + p.y * v1.z + p.z * v2.z + p.w * v3.z;
                acc[i][3] += p.x * v0.w + p.y * v1.w + p.z * v2.w + p.w * v3.w;
            }
        }
    }

    float* Ob = O + (size_t)(b * LSEQ + q0) * DMODEL + h * DHEAD;
#pragma unroll
    for (int i = 0; i < 4; ++i) {
        float inv = 1.f / lrow[i];
        float4 o = make_float4(acc[i][0] * inv, acc[i][1] * inv,
                               acc[i][2] * inv, acc[i][3] * inv);
        *(float4*)(Ob + (size_t)(ty * 4 + i) * DMODEL + tx * 4) = o;
    }
}

// ---------------------------------------------------------------------------
extern "C" void kernel_launch(void* const* d_in, const int* in_sizes, int n_in,
                              void* d_out, int out_size)
{
    const float* query = (const float*)d_in[0];
    const float* key   = (const float*)d_in[1];
    const float* value = (const float*)d_in[2];
    const int*   mask  = (const int*)d_in[3];
    const float* Wq = (const float*)d_in[4];
    const float* bq = (const float*)d_in[5];
    const float* Wk = (const float*)d_in[6];
    const float* bk = (const float*)d_in[7];
    const float* Wv = (const float*)d_in[8];
    const float* bv = (const float*)d_in[9];
    const float* Wo = (const float*)d_in[10];
    const float* bo = (const float*)d_in[11];
    float* out = (float*)d_out;

    float *pQ, *pK, *pV, *pO;
    cudaGetSymbolAddress((void**)&pQ, g_Q);
    cudaGetSymbolAddress((void**)&pK, g_K);
    cudaGetSymbolAddress((void**)&pV, g_V);
    cudaGetSymbolAddress((void**)&pO, g_O);

    const int M = NB * LSEQ;           // 8192
    dim3 gg(DMODEL / 64, M / 64);      // (8, 128)
    dim3 bb(256);

    gemm_nt_bias<<<gg, bb>>>(query, Wq, bq, pQ, M, DMODEL, DMODEL);
    gemm_nt_bias<<<gg, bb>>>(key,   Wk, bk, pK, M, DMODEL, DMODEL);
    gemm_nt_bias<<<gg, bb>>>(value, Wv, bv, pV, M, DMODEL, DMODEL);

    flash_attn<<<dim3(LSEQ / 64, NB * NHEAD), bb>>>(pQ, pK, pV, mask, pO);

    gemm_nt_bias<<<gg, bb>>>(pO, Wo, bo, out, M, DMODEL, DMODEL);
}

// round 17
// speedup vs baseline: 2.1230x; 2.1229x over previous
#include <cuda_runtime.h>
#include <cuda_bf16.h>
#include <cstdint>

#define NB 2
#define LSEQ 4096
#define DMODEL 512
#define NHEAD 8
#define DHEAD 64

static __device__ float g_Q[NB * LSEQ * DMODEL];
static __device__ float g_K[NB * LSEQ * DMODEL];
static __device__ float g_V[NB * LSEQ * DMODEL];
static __device__ float g_O[NB * LSEQ * DMODEL];

// ---------------------------------------------------------------------------
// fp32 NT GEMM with bias (unchanged from R15 — exact precision for projections)
// ---------------------------------------------------------------------------
__global__ __launch_bounds__(256)
void gemm_nt_bias(const float* __restrict__ A, const float* __restrict__ B,
                  const float* __restrict__ bias, float* __restrict__ C,
                  int M, int N, int Kd)
{
    __shared__ float As[64 * 64];
    __shared__ float Bst[64 * 64];

    const int tid = threadIdx.x;
    const int ty = tid >> 4;
    const int tx = tid & 15;
    const int n0 = blockIdx.x * 64;
    const int m0 = blockIdx.y * 64;

    float acc[4][4];
#pragma unroll
    for (int i = 0; i < 4; ++i)
#pragma unroll
        for (int j = 0; j < 4; ++j) acc[i][j] = 0.f;

    for (int kc = 0; kc < Kd; kc += 64) {
        __syncthreads();
#pragma unroll
        for (int e = tid; e < 1024; e += 256) {
            int r  = e >> 4;
            int d4 = (e & 15) << 2;
            float4 av = *(const float4*)(A + (size_t)(m0 + r) * Kd + kc + d4);
            *(float4*)&As[r * 64 + d4] = av;
            float4 bv = *(const float4*)(B + (size_t)(n0 + r) * Kd + kc + d4);
            Bst[(d4 + 0) * 64 + r] = bv.x;
            Bst[(d4 + 1) * 64 + r] = bv.y;
            Bst[(d4 + 2) * 64 + r] = bv.z;
            Bst[(d4 + 3) * 64 + r] = bv.w;
        }
        __syncthreads();

#pragma unroll
        for (int k = 0; k < 64; k += 4) {
            float4 b0 = *(const float4*)&Bst[(k + 0) * 64 + tx * 4];
            float4 b1 = *(const float4*)&Bst[(k + 1) * 64 + tx * 4];
            float4 b2 = *(const float4*)&Bst[(k + 2) * 64 + tx * 4];
            float4 b3 = *(const float4*)&Bst[(k + 3) * 64 + tx * 4];
#pragma unroll
            for (int i = 0; i < 4; ++i) {
                float4 a = *(const float4*)&As[(ty * 4 + i) * 64 + k];
                acc[i][0] += a.x * b0.x + a.y * b1.x + a.z * b2.x + a.w * b3.x;
                acc[i][1] += a.x * b0.y + a.y * b1.y + a.z * b2.y + a.w * b3.y;
                acc[i][2] += a.x * b0.z + a.y * b1.z + a.z * b2.z + a.w * b3.z;
                acc[i][3] += a.x * b0.w + a.y * b1.w + a.z * b2.w + a.w * b3.w;
            }
        }
    }

    float4 bi = *(const float4*)(bias + n0 + tx * 4);
#pragma unroll
    for (int i = 0; i < 4; ++i) {
        float4 o = make_float4(acc[i][0] + bi.x, acc[i][1] + bi.y,
                               acc[i][2] + bi.z, acc[i][3] + bi.w);
        *(float4*)(C + (size_t)(m0 + ty * 4 + i) * N + n0 + tx * 4) = o;
    }
}

// ---------------------------------------------------------------------------
// tf32 helpers
// ---------------------------------------------------------------------------
__device__ __forceinline__ unsigned f2tf(float f)
{
    unsigned u;
    asm("cvt.rna.tf32.f32 %0, %1;" : "=r"(u) : "f"(f));
    return u;
}

__device__ __forceinline__ void mma_tf32(float c[4],
                                         unsigned a0, unsigned a1,
                                         unsigned a2, unsigned a3,
                                         unsigned b0, unsigned b1)
{
    asm volatile(
        "mma.sync.aligned.m16n8k8.row.col.f32.tf32.tf32.f32 "
        "{%0,%1,%2,%3}, {%4,%5,%6,%7}, {%8,%9}, {%0,%1,%2,%3};"
        : "+f"(c[0]), "+f"(c[1]), "+f"(c[2]), "+f"(c[3])
        : "r"(a0), "r"(a1), "r"(a2), "r"(a3), "r"(b0), "r"(b1));
}

// ---------------------------------------------------------------------------
// Flash attention with tf32 tensor-core mma.
// Block: 256 threads (8 warps). Q tile = 128 rows, K/V tile = 64 keys.
// Warp w owns q-rows [16w, 16w+16). Q held entirely in A-fragments (regs).
// Ks[key][d] = col-major B for QK^T; Vt[d][key] = col-major B for PV.
// P stays in registers: C-frag -> A-frag via shuffles.
// ---------------------------------------------------------------------------
#define SPAD 68   // stride: 68 mod 32 == 4 -> conflict-free fragment reads

__global__ __launch_bounds__(256, 2)
void flash_attn_tc(const float* __restrict__ Q, const float* __restrict__ K,
                   const float* __restrict__ V, const int* __restrict__ mask,
                   float* __restrict__ O)
{
    __shared__ unsigned Ks[64 * SPAD];
    __shared__ unsigned Vt[64 * SPAD];
    __shared__ int Ms[64];

    const int tid  = threadIdx.x;
    const int w    = tid >> 5;
    const int lane = tid & 31;
    const int g    = lane >> 2;   // groupID (row within strip / n within tile)
    const int tg   = lane & 3;    // threadID-in-group
    const int b    = blockIdx.y >> 3;
    const int h    = blockIdx.y & 7;
    const int q0   = blockIdx.x * 128;

    const float* Qb = Q + ((size_t)(b * LSEQ) + q0) * DMODEL + h * DHEAD;
    const float* Kb = K + (size_t)b * LSEQ * DMODEL + h * DHEAD;
    const float* Vb = V + (size_t)b * LSEQ * DMODEL + h * DHEAD;
    const int*   mb = mask + b * LSEQ;

    // Q A-fragments for the whole head-dim (8 k-steps), loaded once.
    unsigned aq[8][4];
    {
        const float* qr0 = Qb + (size_t)(16 * w + g) * DMODEL;
        const float* qr1 = qr0 + (size_t)8 * DMODEL;
#pragma unroll
        for (int kk = 0; kk < 8; ++kk) {
            aq[kk][0] = f2tf(qr0[kk * 8 + tg]);
            aq[kk][1] = f2tf(qr1[kk * 8 + tg]);
            aq[kk][2] = f2tf(qr0[kk * 8 + tg + 4]);
            aq[kk][3] = f2tf(qr1[kk * 8 + tg + 4]);
        }
    }

    float oacc[8][4];
#pragma unroll
    for (int j = 0; j < 8; ++j)
#pragma unroll
        for (int r = 0; r < 4; ++r) oacc[j][r] = 0.f;

    float m0 = -1e30f, m1 = -1e30f, l0 = 0.f, l1 = 0.f;

    for (int kt = 0; kt < LSEQ; kt += 64) {
        __syncthreads();
        // Load K tile -> Ks[key][d]; V tile transposed -> Vt[d][key].
#pragma unroll
        for (int e = tid; e < 1024; e += 256) {
            int r  = e >> 4;
            int c4 = (e & 15) << 2;
            float4 kv = *(const float4*)(Kb + (size_t)(kt + r) * DMODEL + c4);
            unsigned* kp = &Ks[r * SPAD + c4];
            kp[0] = f2tf(kv.x); kp[1] = f2tf(kv.y);
            kp[2] = f2tf(kv.z); kp[3] = f2tf(kv.w);
            float4 vv = *(const float4*)(Vb + (size_t)(kt + r) * DMODEL + c4);
            Vt[(c4 + 0) * SPAD + r] = f2tf(vv.x);
            Vt[(c4 + 1) * SPAD + r] = f2tf(vv.y);
            Vt[(c4 + 2) * SPAD + r] = f2tf(vv.z);
            Vt[(c4 + 3) * SPAD + r] = f2tf(vv.w);
        }
        if (tid < 16) *(int4*)&Ms[tid * 4] = *(const int4*)(mb + kt + tid * 4);
        __syncthreads();

        // ---- S = Q K^T : warp strip 16 x 64 ----
        float sacc[8][4];
#pragma unroll
        for (int j = 0; j < 8; ++j)
#pragma unroll
            for (int r = 0; r < 4; ++r) sacc[j][r] = 0.f;

#pragma unroll
        for (int kk = 0; kk < 8; ++kk) {
#pragma unroll
            for (int j = 0; j < 8; ++j) {
                unsigned b0 = Ks[(8 * j + g) * SPAD + kk * 8 + tg];
                unsigned b1 = Ks[(8 * j + g) * SPAD + kk * 8 + tg + 4];
                mma_tf32(sacc[j], aq[kk][0], aq[kk][1], aq[kk][2], aq[kk][3],
                         b0, b1);
            }
        }

        // ---- scale + mask + row max ----
        float rm0 = -1e30f, rm1 = -1e30f;
#pragma unroll
        for (int j = 0; j < 8; ++j) {
            int mk0 = Ms[8 * j + 2 * tg];
            int mk1 = Ms[8 * j + 2 * tg + 1];
            sacc[j][0] = mk0 ? sacc[j][0] * 0.125f : -1000000000.0f;
            sacc[j][1] = mk1 ? sacc[j][1] * 0.125f : -1000000000.0f;
            sacc[j][2] = mk0 ? sacc[j][2] * 0.125f : -1000000000.0f;
            sacc[j][3] = mk1 ? sacc[j][3] * 0.125f : -1000000000.0f;
            rm0 = fmaxf(rm0, fmaxf(sacc[j][0], sacc[j][1]));
            rm1 = fmaxf(rm1, fmaxf(sacc[j][2], sacc[j][3]));
        }
        rm0 = fmaxf(rm0, __shfl_xor_sync(0xffffffffu, rm0, 1));
        rm0 = fmaxf(rm0, __shfl_xor_sync(0xffffffffu, rm0, 2));
        rm1 = fmaxf(rm1, __shfl_xor_sync(0xffffffffu, rm1, 1));
        rm1 = fmaxf(rm1, __shfl_xor_sync(0xffffffffu, rm1, 2));

        // ---- online softmax update ----
        float mn0 = fmaxf(m0, rm0), mn1 = fmaxf(m1, rm1);
        float cr0 = __expf(m0 - mn0), cr1 = __expf(m1 - mn1);
        m0 = mn0; m1 = mn1;
        float rs0 = 0.f, rs1 = 0.f;
#pragma unroll
        for (int j = 0; j < 8; ++j) {
            sacc[j][0] = __expf(sacc[j][0] - mn0);
            sacc[j][1] = __expf(sacc[j][1] - mn0);
            sacc[j][2] = __expf(sacc[j][2] - mn1);
            sacc[j][3] = __expf(sacc[j][3] - mn1);
            rs0 += sacc[j][0] + sacc[j][1];
            rs1 += sacc[j][2] + sacc[j][3];
        }
        rs0 += __shfl_xor_sync(0xffffffffu, rs0, 1);
        rs0 += __shfl_xor_sync(0xffffffffu, rs0, 2);
        rs1 += __shfl_xor_sync(0xffffffffu, rs1, 1);
        rs1 += __shfl_xor_sync(0xffffffffu, rs1, 2);
        l0 = l0 * cr0 + rs0;
        l1 = l1 * cr1 + rs1;
#pragma unroll
        for (int j = 0; j < 8; ++j) {
            oacc[j][0] *= cr0; oacc[j][1] *= cr0;
            oacc[j][2] *= cr1; oacc[j][3] *= cr1;
        }

        // ---- O += P V : C-frag -> A-frag via shuffles, then mma ----
        const int ls0 = (lane & ~3) | (tg >> 1);
        const int ls1 = ls0 + 2;
        const bool eo = (tg & 1);
#pragma unroll
        for (int kk = 0; kk < 8; ++kk) {
            float v00 = __shfl_sync(0xffffffffu, sacc[kk][0], ls0);
            float v01 = __shfl_sync(0xffffffffu, sacc[kk][1], ls0);
            float v20 = __shfl_sync(0xffffffffu, sacc[kk][2], ls0);
            float v21 = __shfl_sync(0xffffffffu, sacc[kk][3], ls0);
            float w00 = __shfl_sync(0xffffffffu, sacc[kk][0], ls1);
            float w01 = __shfl_sync(0xffffffffu, sacc[kk][1], ls1);
            float w20 = __shfl_sync(0xffffffffu, sacc[kk][2], ls1);
            float w21 = __shfl_sync(0xffffffffu, sacc[kk][3], ls1);
            unsigned a0 = f2tf(eo ? v01 : v00);
            unsigned a1 = f2tf(eo ? v21 : v20);
            unsigned a2 = f2tf(eo ? w01 : w00);
            unsigned a3 = f2tf(eo ? w21 : w20);
#pragma unroll
            for (int j = 0; j < 8; ++j) {
                unsigned b0 = Vt[(8 * j + g) * SPAD + kk * 8 + tg];
                unsigned b1 = Vt[(8 * j + g) * SPAD + kk * 8 + tg + 4];
                mma_tf32(oacc[j], a0, a1, a2, a3, b0, b1);
            }
        }
    }

    // ---- epilogue: normalize, write ----
    float inv0 = 1.f / l0, inv1 = 1.f / l1;
    float* Ob = O + ((size_t)(b * LSEQ) + q0 + 16 * w + g) * DMODEL + h * DHEAD;
#pragma unroll
    for (int j = 0; j < 8; ++j) {
        *(float2*)(Ob + 8 * j + 2 * tg) =
            make_float2(oacc[j][0] * inv0, oacc[j][1] * inv0);
        *(float2*)(Ob + (size_t)8 * DMODEL + 8 * j + 2 * tg) =
            make_float2(oacc[j][2] * inv1, oacc[j][3] * inv1);
    }
}

// ---------------------------------------------------------------------------
extern "C" void kernel_launch(void* const* d_in, const int* in_sizes, int n_in,
                              void* d_out, int out_size)
{
    const float* query = (const float*)d_in[0];
    const float* key   = (const float*)d_in[1];
    const float* value = (const float*)d_in[2];
    const int*   mask  = (const int*)d_in[3];
    const float* Wq = (const float*)d_in[4];
    const float* bq = (const float*)d_in[5];
    const float* Wk = (const float*)d_in[6];
    const float* bk = (const float*)d_in[7];
    const float* Wv = (const float*)d_in[8];
    const float* bv = (const float*)d_in[9];
    const float* Wo = (const float*)d_in[10];
    const float* bo = (const float*)d_in[11];
    float* out = (float*)d_out;

    float *pQ, *pK, *pV, *pO;
    cudaGetSymbolAddress((void**)&pQ, g_Q);
    cudaGetSymbolAddress((void**)&pK, g_K);
    cudaGetSymbolAddress((void**)&pV, g_V);
    cudaGetSymbolAddress((void**)&pO, g_O);

    const int M = NB * LSEQ;           // 8192
    dim3 gg(DMODEL / 64, M / 64);      // (8, 128)
    dim3 bb(256);

    gemm_nt_bias<<<gg, bb>>>(query, Wq, bq, pQ, M, DMODEL, DMODEL);
    gemm_nt_bias<<<gg, bb>>>(key,   Wk, bk, pK, M, DMODEL, DMODEL);
    gemm_nt_bias<<<gg, bb>>>(value, Wv, bv, pV, M, DMODEL, DMODEL);

    flash_attn_tc<<<dim3(LSEQ / 128, NB * NHEAD), bb>>>(pQ, pK, pV, mask, pO);

    gemm_nt_bias<<<gg, bb>>>(pO, Wo, bo, out, M, DMODEL, DMODEL);
}